// round 2
// baseline (speedup 1.0000x reference)
#include <cuda_runtime.h>
#include <math.h>

#define Nn 256
#define Mm 32768
#define Dd 384
#define ALPHA 20.0f
#define STOPTHR 0.005f
#define LOG_A (-5.545177444479562f)   /* log(1/256 + 1e-30) */
#define LOG_B (-10.397207708399179f)  /* log(1/32768 + 1e-30) */
#define AA 0.00390625f
#define BB 3.0517578125e-05f
#define NEGBIG (-3.0e38f)

// ---------------- device state (scratch) ----------------
__device__ float    g_logK0[(size_t)Nn * Mm];   // 33.5 MB, L2-resident
__device__ float    g_xn[Nn];
__device__ float    g_yn[Mm];
__device__ float    g_logu[Nn];
__device__ float    g_logv[Mm];
__device__ float    g_cumu[Nn];
__device__ float    g_cumv[Mm];
__device__ unsigned g_errbits;                  // float bits, atomicMax (vals >= 0)
__device__ int      g_done;

// ---------------- init ----------------
__global__ void k_init(float* out) {
    int idx = blockIdx.x * blockDim.x + threadIdx.x;
    if (idx < Mm) { g_logv[idx] = 0.f; g_cumv[idx] = 0.f; }
    if (idx < Nn) { g_logu[idx] = 0.f; g_cumu[idx] = 0.f; }
    if (idx == 0) { g_errbits = 0u; g_done = 0; out[0] = 0.f; }
}

// ---------------- row norms ----------------
__global__ void k_xnorm(const float* __restrict__ x) {
    int i = blockIdx.x;               // 256 blocks, 128 threads
    float s = 0.f;
    for (int k = threadIdx.x; k < Dd; k += 128) {
        float v = x[(size_t)i * Dd + k];
        s = fmaf(v, v, s);
    }
    #pragma unroll
    for (int o = 16; o; o >>= 1) s += __shfl_xor_sync(0xffffffffu, s, o);
    __shared__ float sh[4];
    if ((threadIdx.x & 31) == 0) sh[threadIdx.x >> 5] = s;
    __syncthreads();
    if (threadIdx.x == 0) g_xn[i] = sh[0] + sh[1] + sh[2] + sh[3];
}

__global__ void k_ynorm(const float* __restrict__ y) {
    int row  = blockIdx.x * 8 + (threadIdx.x >> 5);   // warp per row
    int lane = threadIdx.x & 31;
    float s = 0.f;
    for (int k = lane; k < Dd; k += 32) {
        float v = y[(size_t)row * Dd + k];
        s = fmaf(v, v, s);
    }
    #pragma unroll
    for (int o = 16; o; o >>= 1) s += __shfl_xor_sync(0xffffffffu, s, o);
    if (lane == 0) g_yn[row] = s;
}

// ---------------- logK0 = -ALPHA*(xn_i + yn_j) + 2*ALPHA*(x_i . y_j) ----------------
__global__ void k_gemm(const float* __restrict__ x, const float* __restrict__ y) {
    const int BM = 64, BN = 64, BK = 16;
    __shared__ float As[BK][BM];
    __shared__ float Bs[BK][BN];
    int bi = blockIdx.y * BM;
    int bj = blockIdx.x * BN;
    int tid = threadIdx.x;            // 256
    int tr = tid >> 4, tc = tid & 15; // 16x16 threads, 4x4 micro-tile
    int lrow = tid >> 2;              // 0..63
    int lk   = (tid & 3) * 4;         // 0,4,8,12
    const float* xp = x + (size_t)(bi + lrow) * Dd + lk;
    const float* yp = y + (size_t)(bj + lrow) * Dd + lk;

    float acc[4][4];
    #pragma unroll
    for (int r = 0; r < 4; r++)
        #pragma unroll
        for (int c = 0; c < 4; c++) acc[r][c] = 0.f;

    for (int k0 = 0; k0 < Dd; k0 += BK) {
        float4 a4 = *(const float4*)(xp + k0);
        float4 b4 = *(const float4*)(yp + k0);
        As[lk + 0][lrow] = a4.x; As[lk + 1][lrow] = a4.y;
        As[lk + 2][lrow] = a4.z; As[lk + 3][lrow] = a4.w;
        Bs[lk + 0][lrow] = b4.x; Bs[lk + 1][lrow] = b4.y;
        Bs[lk + 2][lrow] = b4.z; Bs[lk + 3][lrow] = b4.w;
        __syncthreads();
        #pragma unroll
        for (int kk = 0; kk < BK; kk++) {
            float4 av = *(const float4*)&As[kk][tr * 4];
            float4 bv = *(const float4*)&Bs[kk][tc * 4];
            acc[0][0] = fmaf(av.x, bv.x, acc[0][0]);
            acc[0][1] = fmaf(av.x, bv.y, acc[0][1]);
            acc[0][2] = fmaf(av.x, bv.z, acc[0][2]);
            acc[0][3] = fmaf(av.x, bv.w, acc[0][3]);
            acc[1][0] = fmaf(av.y, bv.x, acc[1][0]);
            acc[1][1] = fmaf(av.y, bv.y, acc[1][1]);
            acc[1][2] = fmaf(av.y, bv.z, acc[1][2]);
            acc[1][3] = fmaf(av.y, bv.w, acc[1][3]);
            acc[2][0] = fmaf(av.z, bv.x, acc[2][0]);
            acc[2][1] = fmaf(av.z, bv.y, acc[2][1]);
            acc[2][2] = fmaf(av.z, bv.z, acc[2][2]);
            acc[2][3] = fmaf(av.z, bv.w, acc[2][3]);
            acc[3][0] = fmaf(av.w, bv.x, acc[3][0]);
            acc[3][1] = fmaf(av.w, bv.y, acc[3][1]);
            acc[3][2] = fmaf(av.w, bv.z, acc[3][2]);
            acc[3][3] = fmaf(av.w, bv.w, acc[3][3]);
        }
        __syncthreads();
    }

    int j = bj + tc * 4;
    float yn0 = g_yn[j + 0], yn1 = g_yn[j + 1], yn2 = g_yn[j + 2], yn3 = g_yn[j + 3];
    #pragma unroll
    for (int r = 0; r < 4; r++) {
        int i = bi + tr * 4 + r;
        float xc = -ALPHA * g_xn[i];
        float4 o;
        o.x = fmaf(2.f * ALPHA, acc[r][0], xc - ALPHA * yn0);
        o.y = fmaf(2.f * ALPHA, acc[r][1], xc - ALPHA * yn1);
        o.z = fmaf(2.f * ALPHA, acc[r][2], xc - ALPHA * yn2);
        o.w = fmaf(2.f * ALPHA, acc[r][3], xc - ALPHA * yn3);
        *(float4*)(g_logK0 + (size_t)i * Mm + j) = o;
    }
}

// ---------------- column LSE pass (marg=0: logv update; marg=1: col-marginal err) ----------------
__global__ void k_col(int marg) {
    if (g_done) return;
    __shared__ float su[Nn];
    __shared__ float shm[8][33];
    __shared__ float shs[8][33];
    int tid = threadIdx.x;            // 256
    su[tid] = marg ? g_cumu[tid] : g_logu[tid];
    __syncthreads();
    int lane = tid & 31, grp = tid >> 5;
    int j = blockIdx.x * 32 + lane;   // 1024 blocks
    const float* base = g_logK0 + (size_t)(grp * 32) * Mm + j;

    float mx = NEGBIG;
    #pragma unroll 8
    for (int k = 0; k < 32; k++)
        mx = fmaxf(mx, base[(size_t)k * Mm] + su[grp * 32 + k]);
    float s = 0.f;
    #pragma unroll 8
    for (int k = 0; k < 32; k++)
        s += __expf(base[(size_t)k * Mm] + su[grp * 32 + k] - mx);

    shm[grp][lane] = mx; shs[grp][lane] = s;
    __syncthreads();
    if (grp == 0) {
        float M2 = shm[0][lane];
        #pragma unroll
        for (int g = 1; g < 8; g++) M2 = fmaxf(M2, shm[g][lane]);
        float S2 = 0.f;
        #pragma unroll
        for (int g = 0; g < 8; g++) S2 += shs[g][lane] * __expf(shm[g][lane] - M2);
        float lse = M2 + logf(S2);
        if (!marg) {
            g_logv[j] = LOG_B - lse;
        } else {
            float diff = fabsf(expf(g_cumv[j] + lse) - BB);
            #pragma unroll
            for (int o = 16; o; o >>= 1)
                diff = fmaxf(diff, __shfl_xor_sync(0xffffffffu, diff, o));
            if (lane == 0) atomicMax(&g_errbits, __float_as_uint(diff));
        }
    }
}

// ---------------- row LSE pass (marg=0: logu update; marg=1: row-marginal err) ----------------
__global__ void k_row(int marg) {
    if (g_done) return;
    int i = blockIdx.x;               // 256 blocks, 512 threads
    const float* row = g_logK0 + (size_t)i * Mm;
    const float* vv  = marg ? g_cumv : g_logv;
    int tid = threadIdx.x;
    __shared__ float sh[16];

    float mx = NEGBIG;
    for (int j = tid; j < Mm; j += 512) mx = fmaxf(mx, row[j] + vv[j]);
    #pragma unroll
    for (int o = 16; o; o >>= 1) mx = fmaxf(mx, __shfl_xor_sync(0xffffffffu, mx, o));
    if ((tid & 31) == 0) sh[tid >> 5] = mx;
    __syncthreads();
    if (tid < 32) {
        float v = (tid < 16) ? sh[tid] : NEGBIG;
        #pragma unroll
        for (int o = 8; o; o >>= 1) v = fmaxf(v, __shfl_xor_sync(0xffffffffu, v, o));
        if (tid == 0) sh[0] = v;
    }
    __syncthreads();
    float MX = sh[0];
    __syncthreads();

    float s = 0.f;
    for (int j = tid; j < Mm; j += 512) s += __expf(row[j] + vv[j] - MX);
    #pragma unroll
    for (int o = 16; o; o >>= 1) s += __shfl_xor_sync(0xffffffffu, s, o);
    if ((tid & 31) == 0) sh[tid >> 5] = s;
    __syncthreads();
    if (tid == 0) {
        float S = 0.f;
        #pragma unroll
        for (int w = 0; w < 16; w++) S += sh[w];
        float lse = MX + logf(S);
        if (!marg) {
            g_logu[i] = LOG_A - lse;
        } else {
            float diff = fabsf(expf(g_cumu[i] + lse) - AA);
            atomicMax(&g_errbits, __float_as_uint(diff));
        }
    }
}

// ---------------- absorb: cum += scalings, scalings = 0, reset err ----------------
__global__ void k_absorb() {
    if (g_done) return;
    int idx = blockIdx.x * blockDim.x + threadIdx.x;
    if (idx < Mm) { g_cumv[idx] += g_logv[idx]; g_logv[idx] = 0.f; }
    if (idx < Nn) { g_cumu[idx] += g_logu[idx]; g_logu[idx] = 0.f; }
    if (idx == 0) g_errbits = 0u;
}

__global__ void k_fin() {
    if (g_done) return;
    if (__uint_as_float(g_errbits) <= STOPTHR) g_done = 1;
}

// ---------------- transp + loss ----------------
__global__ void k_transp(float* out) {
    __shared__ float su[Nn];
    __shared__ float red[8];
    int tid = threadIdx.x;            // 256
    su[tid] = g_cumu[tid] + g_logu[tid];
    __syncthreads();
    float part = 0.f;
    const unsigned total = (unsigned)Nn * Mm;
    for (unsigned idx = blockIdx.x * 256u + tid; idx < total; idx += gridDim.x * 256u) {
        unsigned i = idx >> 15;              // Mm = 2^15
        unsigned j = idx & (Mm - 1);
        float lk0 = g_logK0[idx];
        float t = __expf(lk0 + su[i] + (g_cumv[j] + g_logv[j]));
        out[1 + idx] = t;
        part = fmaf(t, lk0, part);           // accumulate t * logK0; scale by -1/ALPHA later
    }
    #pragma unroll
    for (int o = 16; o; o >>= 1) part += __shfl_xor_sync(0xffffffffu, part, o);
    if ((tid & 31) == 0) red[tid >> 5] = part;
    __syncthreads();
    if (tid == 0) {
        float S = 0.f;
        #pragma unroll
        for (int w = 0; w < 8; w++) S += red[w];
        atomicAdd(out, S * (-1.f / ALPHA));
    }
}

// ---------------- launch ----------------
extern "C" void kernel_launch(void* const* d_in, const int* in_sizes, int n_in,
                              void* d_out, int out_size) {
    const float* x = (const float*)d_in[0];   // [256, 384]
    const float* y = (const float*)d_in[1];   // [32768, 384]
    float* out = (float*)d_out;               // [0]=loss, [1..]=transp (row-major 256x32768)

    k_init <<<(Mm + 255) / 256, 256>>>(out);
    k_xnorm<<<Nn, 128>>>(x);
    k_ynorm<<<Mm / 8, 256>>>(y);
    k_gemm <<<dim3(Mm / 64, Nn / 64), 256>>>(x, y);

    for (int t = 1; t <= 100; t++) {
        k_col<<<Mm / 32, 256>>>(0);
        k_row<<<Nn, 512>>>(0);
        if (t % 50 == 1) {                    // absorption + convergence check (t = 1, 51)
            k_absorb<<<(Mm + 255) / 256, 256>>>();
            k_row<<<Nn, 512>>>(1);
            k_col<<<Mm / 32, 256>>>(1);
            k_fin<<<1, 1>>>();
        }
    }

    k_transp<<<4096, 256>>>(out);
}

// round 3
// speedup vs baseline: 1.7689x; 1.7689x over previous
#include <cuda_runtime.h>
#include <math.h>

#define Nn 256
#define Mm 32768
#define Dd 384
#define ALPHA 20.0f
#define STOPTHR 0.005f
#define LOG_A (-5.545177444479562f)   /* log(1/256 + 1e-30) */
#define LOG_B (-10.397207708399179f)  /* log(1/32768 + 1e-30) */
#define AA 0.00390625f
#define BB 3.0517578125e-05f
#define NEGBIG (-3.0e38f)

#define NB 128           /* persistent grid: 128 blocks x 256 threads = 32768 threads */
#define NT 256

// ---------------- device state (scratch) ----------------
__device__ float    g_logK0[(size_t)Nn * Mm];   // 33.5 MB, L2-resident
__device__ float    g_xn[Nn];
__device__ float    g_yn[Mm];
__device__ float    g_logu[Nn];
__device__ float    g_logv[Mm];
__device__ float    g_cumu[Nn];
__device__ float    g_cumv[Mm];
__device__ unsigned g_errbits;                  // float bits, atomicMax (vals >= 0)
__device__ int      g_done;
__device__ volatile unsigned g_barcnt;          // grid barrier monotonic counter

// ---------------- init ----------------
__global__ void k_init(float* out) {
    int idx = blockIdx.x * blockDim.x + threadIdx.x;
    if (idx < Mm) { g_logv[idx] = 0.f; g_cumv[idx] = 0.f; }
    if (idx < Nn) { g_logu[idx] = 0.f; g_cumu[idx] = 0.f; }
    if (idx == 0) { g_errbits = 0u; g_done = 0; g_barcnt = 0u; out[0] = 0.f; }
}

// ---------------- row norms ----------------
__global__ void k_xnorm(const float* __restrict__ x) {
    int i = blockIdx.x;               // 256 blocks, 128 threads
    float s = 0.f;
    for (int k = threadIdx.x; k < Dd; k += 128) {
        float v = x[(size_t)i * Dd + k];
        s = fmaf(v, v, s);
    }
    #pragma unroll
    for (int o = 16; o; o >>= 1) s += __shfl_xor_sync(0xffffffffu, s, o);
    __shared__ float sh[4];
    if ((threadIdx.x & 31) == 0) sh[threadIdx.x >> 5] = s;
    __syncthreads();
    if (threadIdx.x == 0) g_xn[i] = sh[0] + sh[1] + sh[2] + sh[3];
}

__global__ void k_ynorm(const float* __restrict__ y) {
    int row  = blockIdx.x * 8 + (threadIdx.x >> 5);   // warp per row
    int lane = threadIdx.x & 31;
    float s = 0.f;
    for (int k = lane; k < Dd; k += 32) {
        float v = y[(size_t)row * Dd + k];
        s = fmaf(v, v, s);
    }
    #pragma unroll
    for (int o = 16; o; o >>= 1) s += __shfl_xor_sync(0xffffffffu, s, o);
    if (lane == 0) g_yn[row] = s;
}

// ---------------- logK0 = -ALPHA*(xn_i + yn_j) + 2*ALPHA*(x_i . y_j) ----------------
__global__ void k_gemm(const float* __restrict__ x, const float* __restrict__ y) {
    const int BM = 64, BN = 64, BK = 16;
    __shared__ float As[BK][BM];
    __shared__ float Bs[BK][BN];
    int bi = blockIdx.y * BM;
    int bj = blockIdx.x * BN;
    int tid = threadIdx.x;            // 256
    int tr = tid >> 4, tc = tid & 15; // 16x16 threads, 4x4 micro-tile
    int lrow = tid >> 2;              // 0..63
    int lk   = (tid & 3) * 4;         // 0,4,8,12
    const float* xp = x + (size_t)(bi + lrow) * Dd + lk;
    const float* yp = y + (size_t)(bj + lrow) * Dd + lk;

    float acc[4][4];
    #pragma unroll
    for (int r = 0; r < 4; r++)
        #pragma unroll
        for (int c = 0; c < 4; c++) acc[r][c] = 0.f;

    for (int k0 = 0; k0 < Dd; k0 += BK) {
        float4 a4 = *(const float4*)(xp + k0);
        float4 b4 = *(const float4*)(yp + k0);
        As[lk + 0][lrow] = a4.x; As[lk + 1][lrow] = a4.y;
        As[lk + 2][lrow] = a4.z; As[lk + 3][lrow] = a4.w;
        Bs[lk + 0][lrow] = b4.x; Bs[lk + 1][lrow] = b4.y;
        Bs[lk + 2][lrow] = b4.z; Bs[lk + 3][lrow] = b4.w;
        __syncthreads();
        #pragma unroll
        for (int kk = 0; kk < BK; kk++) {
            float4 av = *(const float4*)&As[kk][tr * 4];
            float4 bv = *(const float4*)&Bs[kk][tc * 4];
            acc[0][0] = fmaf(av.x, bv.x, acc[0][0]);
            acc[0][1] = fmaf(av.x, bv.y, acc[0][1]);
            acc[0][2] = fmaf(av.x, bv.z, acc[0][2]);
            acc[0][3] = fmaf(av.x, bv.w, acc[0][3]);
            acc[1][0] = fmaf(av.y, bv.x, acc[1][0]);
            acc[1][1] = fmaf(av.y, bv.y, acc[1][1]);
            acc[1][2] = fmaf(av.y, bv.z, acc[1][2]);
            acc[1][3] = fmaf(av.y, bv.w, acc[1][3]);
            acc[2][0] = fmaf(av.z, bv.x, acc[2][0]);
            acc[2][1] = fmaf(av.z, bv.y, acc[2][1]);
            acc[2][2] = fmaf(av.z, bv.z, acc[2][2]);
            acc[2][3] = fmaf(av.z, bv.w, acc[2][3]);
            acc[3][0] = fmaf(av.w, bv.x, acc[3][0]);
            acc[3][1] = fmaf(av.w, bv.y, acc[3][1]);
            acc[3][2] = fmaf(av.w, bv.z, acc[3][2]);
            acc[3][3] = fmaf(av.w, bv.w, acc[3][3]);
        }
        __syncthreads();
    }

    int j = bj + tc * 4;
    float yn0 = g_yn[j + 0], yn1 = g_yn[j + 1], yn2 = g_yn[j + 2], yn3 = g_yn[j + 3];
    #pragma unroll
    for (int r = 0; r < 4; r++) {
        int i = bi + tr * 4 + r;
        float xc = -ALPHA * g_xn[i];
        float4 o;
        o.x = fmaf(2.f * ALPHA, acc[r][0], xc - ALPHA * yn0);
        o.y = fmaf(2.f * ALPHA, acc[r][1], xc - ALPHA * yn1);
        o.z = fmaf(2.f * ALPHA, acc[r][2], xc - ALPHA * yn2);
        o.w = fmaf(2.f * ALPHA, acc[r][3], xc - ALPHA * yn3);
        *(float4*)(g_logK0 + (size_t)i * Mm + j) = o;
    }
}

// ============ persistent Sinkhorn ============

__device__ __forceinline__ void gridbar(unsigned& epoch) {
    epoch += NB;                       // uniform across all threads/blocks
    __syncthreads();
    if (threadIdx.x == 0) {
        __threadfence();
        atomicAdd((unsigned*)&g_barcnt, 1u);
        while (g_barcnt < epoch) { }
        __threadfence();
    }
    __syncthreads();
}

// column LSE: one thread per column j. marg=0: logv update; marg=1: col-marginal err
__device__ __forceinline__ void colpass(float* su, int marg) {
    int tid = threadIdx.x;
    su[tid] = marg ? g_cumu[tid] : g_logu[tid];    // NT == Nn == 256
    __syncthreads();
    int j = blockIdx.x * NT + tid;                 // 0..32767
    const float* col = g_logK0 + j;

    float mx = NEGBIG;
    #pragma unroll 8
    for (int i = 0; i < Nn; i++)
        mx = fmaxf(mx, col[(size_t)i * Mm] + su[i]);
    float s = 0.f;
    #pragma unroll 8
    for (int i = 0; i < Nn; i++)
        s += __expf(col[(size_t)i * Mm] + su[i] - mx);
    float lse = mx + logf(s);

    if (!marg) {
        g_logv[j] = LOG_B - lse;
    } else {
        float diff = fabsf(expf(g_cumv[j] + lse) - BB);
        #pragma unroll
        for (int o = 16; o; o >>= 1)
            diff = fmaxf(diff, __shfl_xor_sync(0xffffffffu, diff, o));
        if ((tid & 31) == 0) atomicMax(&g_errbits, __float_as_uint(diff));
    }
    __syncthreads();
}

// row LSE: each block handles 2 rows simultaneously (shares vv loads).
__device__ __forceinline__ void rowpass(float* red, int marg) {
    const float* vv = marg ? g_cumv : g_logv;
    int tid = threadIdx.x;
    int i0 = blockIdx.x * 2;
    const float* r0 = g_logK0 + (size_t)i0 * Mm;
    const float* r1 = r0 + Mm;

    float mx0 = NEGBIG, mx1 = NEGBIG;
    for (int j = tid; j < Mm; j += NT) {
        float v = vv[j];
        mx0 = fmaxf(mx0, r0[j] + v);
        mx1 = fmaxf(mx1, r1[j] + v);
    }
    #pragma unroll
    for (int o = 16; o; o >>= 1) {
        mx0 = fmaxf(mx0, __shfl_xor_sync(0xffffffffu, mx0, o));
        mx1 = fmaxf(mx1, __shfl_xor_sync(0xffffffffu, mx1, o));
    }
    if ((tid & 31) == 0) { red[tid >> 5] = mx0; red[8 + (tid >> 5)] = mx1; }
    __syncthreads();
    float MX0 = red[0], MX1 = red[8];
    #pragma unroll
    for (int w = 1; w < 8; w++) { MX0 = fmaxf(MX0, red[w]); MX1 = fmaxf(MX1, red[8 + w]); }
    __syncthreads();

    float s0 = 0.f, s1 = 0.f;
    for (int j = tid; j < Mm; j += NT) {
        float v = vv[j];
        s0 += __expf(r0[j] + v - MX0);
        s1 += __expf(r1[j] + v - MX1);
    }
    #pragma unroll
    for (int o = 16; o; o >>= 1) {
        s0 += __shfl_xor_sync(0xffffffffu, s0, o);
        s1 += __shfl_xor_sync(0xffffffffu, s1, o);
    }
    if ((tid & 31) == 0) { red[tid >> 5] = s0; red[8 + (tid >> 5)] = s1; }
    __syncthreads();
    if (tid == 0) {
        float S0 = 0.f, S1 = 0.f;
        #pragma unroll
        for (int w = 0; w < 8; w++) { S0 += red[w]; S1 += red[8 + w]; }
        float lse0 = MX0 + logf(S0);
        float lse1 = MX1 + logf(S1);
        if (!marg) {
            g_logu[i0]     = LOG_A - lse0;
            g_logu[i0 + 1] = LOG_A - lse1;
        } else {
            float d = fmaxf(fabsf(expf(g_cumu[i0] + lse0) - AA),
                            fabsf(expf(g_cumu[i0 + 1] + lse1) - AA));
            atomicMax(&g_errbits, __float_as_uint(d));
        }
    }
    __syncthreads();
}

__global__ void __launch_bounds__(NT, 1) k_sink() {
    __shared__ float su[Nn];
    __shared__ float red[16];
    unsigned epoch = 0;
    int gtid = blockIdx.x * NT + threadIdx.x;      // 0..32767 == Mm

    for (int t = 1; t <= 100; t++) {
        colpass(su, 0);                    // logv <- f(logu)
        gridbar(epoch);
        rowpass(red, 0);                   // logu <- f(logv)
        gridbar(epoch);

        if (t % 50 == 1) {
            // absorb: cum += scalings; scalings = 0; reset err
            g_cumv[gtid] += g_logv[gtid];
            g_logv[gtid] = 0.f;
            if (gtid < Nn) { g_cumu[gtid] += g_logu[gtid]; g_logu[gtid] = 0.f; }
            if (gtid == 0) g_errbits = 0u;
            gridbar(epoch);
            rowpass(red, 1);               // row-marginal err
            colpass(su, 1);                // col-marginal err
            gridbar(epoch);
            if (gtid == 0)
                g_done = (__uint_as_float(g_errbits) <= STOPTHR) ? 1 : 0;
            gridbar(epoch);
            if (*(volatile int*)&g_done) break;   // uniform across grid
        }
    }
}

// ---------------- transp + loss ----------------
__global__ void k_transp(float* out) {
    __shared__ float su[Nn];
    __shared__ float red[8];
    int tid = threadIdx.x;            // 256
    su[tid] = g_cumu[tid] + g_logu[tid];
    __syncthreads();
    float part = 0.f;
    const unsigned total = (unsigned)Nn * Mm;
    for (unsigned idx = blockIdx.x * 256u + tid; idx < total; idx += gridDim.x * 256u) {
        unsigned i = idx >> 15;              // Mm = 2^15
        unsigned j = idx & (Mm - 1);
        float lk0 = g_logK0[idx];
        float t = __expf(lk0 + su[i] + (g_cumv[j] + g_logv[j]));
        out[1 + idx] = t;
        part = fmaf(t, lk0, part);           // accumulate t * logK0; scale by -1/ALPHA later
    }
    #pragma unroll
    for (int o = 16; o; o >>= 1) part += __shfl_xor_sync(0xffffffffu, part, o);
    if ((tid & 31) == 0) red[tid >> 5] = part;
    __syncthreads();
    if (tid == 0) {
        float S = 0.f;
        #pragma unroll
        for (int w = 0; w < 8; w++) S += red[w];
        atomicAdd(out, S * (-1.f / ALPHA));
    }
}

// ---------------- launch ----------------
extern "C" void kernel_launch(void* const* d_in, const int* in_sizes, int n_in,
                              void* d_out, int out_size) {
    const float* x = (const float*)d_in[0];   // [256, 384]
    const float* y = (const float*)d_in[1];   // [32768, 384]
    float* out = (float*)d_out;               // [0]=loss, [1..]=transp (row-major 256x32768)

    k_init <<<(Mm + 255) / 256, 256>>>(out);
    k_xnorm<<<Nn, 128>>>(x);
    k_ynorm<<<Mm / 8, 256>>>(y);
    k_gemm <<<dim3(Mm / 64, Nn / 64), 256>>>(x, y);
    k_sink <<<NB, NT>>>();
    k_transp<<<4096, 256>>>(out);
}